// round 3
// baseline (speedup 1.0000x reference)
#include <cuda_runtime.h>
#include <math.h>

// 17 accumulators per batch:
// [0]=sum|w|, [1]=sum w, [2..4]=sum w*X, [5..7]=sum w*Y, [8..16]=sum w*Y_i*X_j
#define NACC 17
#define MAXB 64
__device__ double g_acc[MAXB][NACC];

__global__ void zero_acc_kernel(int B) {
    int i = blockIdx.x * blockDim.x + threadIdx.x;
    if (i < B * NACC) ((double*)g_acc)[i] = 0.0;
}

__global__ void accum_kernel(const float* __restrict__ xyzs1,
                             const float* __restrict__ xyzs2,
                             const int2* __restrict__ pairs,
                             const float* __restrict__ weights,
                             int M, int N) {
    const int b = blockIdx.y;
    const float* __restrict__ X = xyzs1 + (size_t)b * M * 3;
    const float* __restrict__ Y = xyzs2 + (size_t)b * M * 3;
    const int2*  __restrict__ P = pairs + (size_t)b * N;
    const float* __restrict__ W = weights + (size_t)b * N;

    float a[NACC];
#pragma unroll
    for (int k = 0; k < NACC; k++) a[k] = 0.0f;

    const int stride = gridDim.x * blockDim.x;
    for (int n = blockIdx.x * blockDim.x + threadIdx.x; n < N; n += stride) {
        int2 ij = __ldg(&P[n]);
        float w = __ldg(&W[n]);
        const float* px = X + (size_t)ij.x * 3;
        const float* py = Y + (size_t)ij.y * 3;
        float x0 = __ldg(px + 0), x1 = __ldg(px + 1), x2 = __ldg(px + 2);
        float y0 = __ldg(py + 0), y1 = __ldg(py + 1), y2 = __ldg(py + 2);

        a[0] += fabsf(w);
        a[1] += w;
        float wx0 = w * x0, wx1 = w * x1, wx2 = w * x2;
        a[2] += wx0;  a[3] += wx1;  a[4] += wx2;
        a[5] += w * y0; a[6] += w * y1; a[7] += w * y2;
        a[8]  += y0 * wx0; a[9]  += y0 * wx1; a[10] += y0 * wx2;
        a[11] += y1 * wx0; a[12] += y1 * wx1; a[13] += y1 * wx2;
        a[14] += y2 * wx0; a[15] += y2 * wx1; a[16] += y2 * wx2;
    }

    // block reduce: warp shuffle -> shared float partials -> double atomics
    __shared__ float part[NACC];
    if (threadIdx.x < NACC) part[threadIdx.x] = 0.0f;
    __syncthreads();

    const int lane = threadIdx.x & 31;
#pragma unroll
    for (int k = 0; k < NACC; k++) {
        float v = a[k];
#pragma unroll
        for (int off = 16; off > 0; off >>= 1)
            v += __shfl_down_sync(0xffffffffu, v, off);
        if (lane == 0) atomicAdd(&part[k], v);
    }
    __syncthreads();
    if (threadIdx.x < NACC)
        atomicAdd(&g_acc[b][threadIdx.x], (double)part[threadIdx.x]);
}

// ---------------------------------------------------------------------------
// Finalize: per-batch 3x3 weighted Procrustes (double precision).
// Output layout: Rs [B,3,3] | ts [B,3] | ws [B]  (flattened, float32)
// ---------------------------------------------------------------------------
__global__ void finalize_kernel(float* __restrict__ out, int B) {
    int b = blockIdx.x * blockDim.x + threadIdx.x;
    if (b >= B) return;

    double acc[NACC];
#pragma unroll
    for (int k = 0; k < NACC; k++) acc[k] = g_acc[b][k];

    const double EPS = 1.1920928955078125e-07; // float32 eps
    double W1 = acc[0];
    double inv = 1.0 / (W1 + EPS);
    double c   = acc[1] * inv;
    double mux[3] = { acc[2] * inv, acc[3] * inv, acc[4] * inv };
    double muy[3] = { acc[5] * inv, acc[6] * inv, acc[7] * inv };

    double S[3][3];
    double f = 2.0 - c;
#pragma unroll
    for (int i = 0; i < 3; i++)
#pragma unroll
        for (int j = 0; j < 3; j++)
            S[i][j] = acc[8 + 3 * i + j] * inv - f * muy[i] * mux[j];

    // Bm = S^T S  (symmetric PSD)
    double Bm[3][3];
#pragma unroll
    for (int i = 0; i < 3; i++)
#pragma unroll
        for (int j = 0; j < 3; j++)
            Bm[i][j] = S[0][i] * S[0][j] + S[1][i] * S[1][j] + S[2][i] * S[2][j];

    double V[3][3] = {{1,0,0},{0,1,0},{0,0,1}};

    // Jacobi eigendecomposition of Bm (cyclic sweeps)
    for (int sweep = 0; sweep < 30; sweep++) {
        double offd = fabs(Bm[0][1]) + fabs(Bm[0][2]) + fabs(Bm[1][2]);
        double diag = fabs(Bm[0][0]) + fabs(Bm[1][1]) + fabs(Bm[2][2]);
        if (offd <= 1e-15 * (diag + 1e-300)) break;
#pragma unroll
        for (int pair = 0; pair < 3; pair++) {
            int p = (pair == 0) ? 0 : (pair == 1) ? 0 : 1;
            int q = (pair == 0) ? 1 : (pair == 1) ? 2 : 2;
            double bpq = Bm[p][q];
            if (bpq == 0.0) continue;
            double tau = (Bm[q][q] - Bm[p][p]) / (2.0 * bpq);
            double t = copysign(1.0, tau) / (fabs(tau) + sqrt(1.0 + tau * tau));
            double cs = 1.0 / sqrt(1.0 + t * t);
            double sn = t * cs;

            double bpp = Bm[p][p], bqq = Bm[q][q];
            Bm[p][p] = bpp - t * bpq;
            Bm[q][q] = bqq + t * bpq;
            Bm[p][q] = Bm[q][p] = 0.0;
            int r = 3 - p - q;
            double brp = Bm[r][p], brq = Bm[r][q];
            Bm[r][p] = Bm[p][r] = cs * brp - sn * brq;
            Bm[r][q] = Bm[q][r] = sn * brp + cs * brq;
#pragma unroll
            for (int i = 0; i < 3; i++) {
                double vip = V[i][p], viq = V[i][q];
                V[i][p] = cs * vip - sn * viq;
                V[i][q] = sn * vip + cs * viq;
            }
        }
    }

    // sort eigenvalues descending, permute V columns
    double lam[3] = { Bm[0][0], Bm[1][1], Bm[2][2] };
    int idx[3] = {0, 1, 2};
#pragma unroll
    for (int i = 0; i < 2; i++)
#pragma unroll
        for (int j = 0; j < 2 - i; j++)
            if (lam[idx[j]] < lam[idx[j + 1]]) { int tt = idx[j]; idx[j] = idx[j + 1]; idx[j + 1] = tt; }

    double v1[3], v2[3], v3[3];
#pragma unroll
    for (int i = 0; i < 3; i++) {
        v1[i] = V[i][idx[0]];
        v2[i] = V[i][idx[1]];
        v3[i] = V[i][idx[2]];
    }

    // U columns: u1 = S v1 / |.|, u2 = orthonormalized S v2, u3 = u1 x u2
    double u1[3], u2[3], u3[3];
#pragma unroll
    for (int i = 0; i < 3; i++)
        u1[i] = S[i][0] * v1[0] + S[i][1] * v1[1] + S[i][2] * v1[2];
    double n1 = sqrt(u1[0]*u1[0] + u1[1]*u1[1] + u1[2]*u1[2]);
    if (n1 > 1e-150) { u1[0] /= n1; u1[1] /= n1; u1[2] /= n1; }
    else { u1[0] = 1.0; u1[1] = 0.0; u1[2] = 0.0; }

#pragma unroll
    for (int i = 0; i < 3; i++)
        u2[i] = S[i][0] * v2[0] + S[i][1] * v2[1] + S[i][2] * v2[2];
    double d12 = u2[0]*u1[0] + u2[1]*u1[1] + u2[2]*u1[2];
#pragma unroll
    for (int i = 0; i < 3; i++) u2[i] -= d12 * u1[i];
    double n2 = sqrt(u2[0]*u2[0] + u2[1]*u2[1] + u2[2]*u2[2]);
    if (n2 > 1e-150) { u2[0] /= n2; u2[1] /= n2; u2[2] /= n2; }
    else {
        // any unit vector orthogonal to u1
        double ax = fabs(u1[0]), ay = fabs(u1[1]), az = fabs(u1[2]);
        double e[3] = {0,0,0};
        if (ax <= ay && ax <= az) e[0] = 1.0; else if (ay <= az) e[1] = 1.0; else e[2] = 1.0;
        u2[0] = u1[1]*e[2] - u1[2]*e[1];
        u2[1] = u1[2]*e[0] - u1[0]*e[2];
        u2[2] = u1[0]*e[1] - u1[1]*e[0];
        double nn = sqrt(u2[0]*u2[0] + u2[1]*u2[1] + u2[2]*u2[2]);
        u2[0] /= nn; u2[1] /= nn; u2[2] /= nn;
    }
    u3[0] = u1[1]*u2[2] - u1[2]*u2[1];
    u3[1] = u1[2]*u2[0] - u1[0]*u2[2];
    u3[2] = u1[0]*u2[1] - u1[1]*u2[0];

    // PARITY FIX: determinant must be over the SORTED column order [v1|v2|v3],
    // i.e. the same order used in the reconstruction below. Using the unsorted
    // V flips the third dyad's sign whenever the sort is an odd permutation
    // (caused rel_err = sqrt(3)/2 with 9/16 batches flipped).
    double detVs = v1[0] * (v2[1] * v3[2] - v2[2] * v3[1])
                 - v1[1] * (v2[0] * v3[2] - v2[2] * v3[0])
                 + v1[2] * (v2[0] * v3[1] - v2[1] * v3[0]);
    double s3 = (detVs < 0.0) ? -1.0 : 1.0;

    // R = u1 v1^T + u2 v2^T + sign(det[v1 v2 v3]) * (u1 x u2) v3^T
    double R[3][3];
#pragma unroll
    for (int i = 0; i < 3; i++)
#pragma unroll
        for (int j = 0; j < 3; j++)
            R[i][j] = u1[i]*v1[j] + u2[i]*v2[j] + s3 * u3[i]*v3[j];

    double tvec[3];
#pragma unroll
    for (int i = 0; i < 3; i++)
        tvec[i] = muy[i] - (R[i][0]*mux[0] + R[i][1]*mux[1] + R[i][2]*mux[2]);

    // outputs: Rs [B,3,3] | ts [B,3] | ws [B]
#pragma unroll
    for (int i = 0; i < 3; i++)
#pragma unroll
        for (int j = 0; j < 3; j++)
            out[b * 9 + i * 3 + j] = (float)R[i][j];
#pragma unroll
    for (int i = 0; i < 3; i++)
        out[B * 9 + b * 3 + i] = (float)tvec[i];
    out[B * 12 + b] = (float)acc[1];   // ws = sum w
}

extern "C" void kernel_launch(void* const* d_in, const int* in_sizes, int n_in,
                              void* d_out, int out_size) {
    const float* xyzs1   = (const float*)d_in[0];
    const float* xyzs2   = (const float*)d_in[1];
    const int2*  pairs   = (const int2*)d_in[2];
    const float* weights = (const float*)d_in[3];
    float* out = (float*)d_out;

    int B = out_size / 13;              // 9 + 3 + 1 floats per batch
    if (B < 1) B = 1;
    if (B > MAXB) B = MAXB;
    int M = in_sizes[0] / (3 * B);
    int N = in_sizes[3] / B;

    zero_acc_kernel<<<(B * NACC + 127) / 128, 128>>>(B);

    dim3 grid(120, B);
    accum_kernel<<<grid, 256>>>(xyzs1, xyzs2, pairs, weights, M, N);

    finalize_kernel<<<1, 64>>>(out, B);
}